// round 11
// baseline (speedup 1.0000x reference)
#include <cuda_runtime.h>
#include <math.h>

// Problem constants (fixed by reference setup)
#define BD     16      // batch
#define HD     16      // heads
#define DD     128     // head dim
#define BLKD   16      // tokens per cache block
#define MAXBD  128     // blocks per sequence
#define MAXSD  2048    // max sequence length
#define NSPLIT 16      // token splits per (b,hp)
#define CHUNK  128     // tokens per split
#define WTOK   32      // contiguous tokens per warp
#define NHP    (HD/2)  // head pairs
#define SOFTMAX_SCALE 0.088388347648318447f  // 1/sqrt(128)
#define NEGBIG (-1e30f)

// Partial-result scratch (allocation-free: __device__ globals, zero-init .bss)
__device__ float g_pm[BD * HD * NSPLIT];
__device__ float g_pl[BD * HD * NSPLIT];
__device__ float g_pacc[BD * HD * NSPLIT * DD];      // 2 MB
__device__ unsigned int g_cnt[BD * NHP];             // self-resetting counters

// ---------------------------------------------------------------------------
// Split-KV decode attention, 2 heads per warp -> 1KB contiguous DRAM granules.
//  grid (NSPLIT, HD/2, BD), 128 threads = 4 warps.
//  Warp w owns CONTIGUOUS tokens [s0+32w, s0+32w+32) and processes BOTH
//  heads of its CTA's head pair: per token the K touch is heads {h0,h1} =
//  two ADJACENT 512B slices = 1KB contiguous (same for V), doubling the
//  DRAM granule vs one-head-per-warp. Iteration = 2 tokens -> 8 LDG.128.
//  Two independent online-softmax states per warp.
//  KV loads are __ldcs (zero-reuse stream). Empty splits write no scratch;
//  combiner uses nvalid = ceil(L/CHUNK). Fresh token (s == L-1) substitutes
//  register-roped K / raw V. Last split CTA per (b,hp) combines and writes
//  both heads' outputs, then resets its counter (graph-replay deterministic).
// ---------------------------------------------------------------------------
__global__ __launch_bounds__(128, 6) void attn_fused(
    const float* __restrict__ Q,  const float* __restrict__ K,
    const float* __restrict__ V,  const float* __restrict__ Kc,
    const float* __restrict__ Vc, const float* __restrict__ cosb,
    const float* __restrict__ sinb, const float* __restrict__ mask,
    const int* __restrict__ ilen, const int* __restrict__ btab,
    float* __restrict__ out)
{
    const int split = blockIdx.x, hp = blockIdx.y, b = blockIdx.z;
    const int tid = threadIdx.x, warp = tid >> 5, lane = tid & 31;
    const int h0  = 2 * hp;
    const int bh0 = b * HD + h0;                 // head h0 flat index
    const int L  = ilen[b];
    const int s0 = split * CHUNK;

    if (s0 < L) {
        const int s1  = (s0 + CHUNK < L) ? s0 + CHUNK : L;
        const int pos = L - 1;   // fresh-token position

        // --- RoPE on Q and K for both heads (registers) ---
        const float4 c4 = *(const float4*)(cosb + b * DD + 4 * lane);
        const float4 s4 = *(const float4*)(sinb + b * DD + 4 * lane);
        const float sgn = (lane < 16) ? -1.f : 1.f;   // rot = [-x2, x1]

        float4 qr[2], kr[2], vv4[2];
        #pragma unroll
        for (int e = 0; e < 2; e++) {
            const int bhe = bh0 + e;
            const float4 q4 = *(const float4*)(Q + bhe * DD + 4 * lane);
            const float4 k4 = *(const float4*)(K + bhe * DD + 4 * lane);
            vv4[e] = *(const float4*)(V + bhe * DD + 4 * lane);
            float4 qp, kp;
            qp.x = __shfl_xor_sync(~0u, q4.x, 16);  qp.y = __shfl_xor_sync(~0u, q4.y, 16);
            qp.z = __shfl_xor_sync(~0u, q4.z, 16);  qp.w = __shfl_xor_sync(~0u, q4.w, 16);
            kp.x = __shfl_xor_sync(~0u, k4.x, 16);  kp.y = __shfl_xor_sync(~0u, k4.y, 16);
            kp.z = __shfl_xor_sync(~0u, k4.z, 16);  kp.w = __shfl_xor_sync(~0u, k4.w, 16);
            qr[e].x = (q4.x * c4.x + sgn * qp.x * s4.x) * SOFTMAX_SCALE;
            qr[e].y = (q4.y * c4.y + sgn * qp.y * s4.y) * SOFTMAX_SCALE;
            qr[e].z = (q4.z * c4.z + sgn * qp.z * s4.z) * SOFTMAX_SCALE;
            qr[e].w = (q4.w * c4.w + sgn * qp.w * s4.w) * SOFTMAX_SCALE;
            kr[e].x =  k4.x * c4.x + sgn * kp.x * s4.x;
            kr[e].y =  k4.y * c4.y + sgn * kp.y * s4.y;
            kr[e].z =  k4.z * c4.z + sgn * kp.z * s4.z;
            kr[e].w =  k4.w * c4.w + sgn * kp.w * s4.w;
        }

        const float* mk  = mask + b * MAXSD;
        const int    ws0 = s0 + WTOK * warp;          // warp's first token

        float  m0 = NEGBIG, l0 = 0.f, m1 = NEGBIG, l1 = 0.f;
        float4 acc0 = make_float4(0.f, 0.f, 0.f, 0.f);
        float4 acc1 = make_float4(0.f, 0.f, 0.f, 0.f);

        if (ws0 < s1) {
            // hoist the warp's two block-table entries (tokens ws0..ws0+31)
            const int* bt = btab + b * MAXBD;
            const int  e0 = __ldg(bt + (ws0 >> 4));
            const int  e1 = __ldg(bt + (ws0 >> 4) + 1);

            #pragma unroll
            for (int k = 0; k < WTOK / 2; k++) {
                const int tb = ws0 + 2 * k;           // 2 consecutive tokens
                if (tb >= s1) break;                  // warp-uniform exit

                // tb even -> tb, tb+1 in the same 16-token block
                const int e   = (k < 8) ? e0 : e1;
                const int row = e * BLKD + (tb & 15);
                const int off = (row * HD + h0) * DD + 4 * lane;

                // kk/vv: [t0h0, t0h1, t1h0, t1h1]; {t,h0},{t,h1} = 1KB run
                float4 kk[4], vvv[4];
                kk[0]  = __ldcs((const float4*)(Kc + off));
                kk[1]  = __ldcs((const float4*)(Kc + off + DD));
                kk[2]  = __ldcs((const float4*)(Kc + off + HD * DD));
                kk[3]  = __ldcs((const float4*)(Kc + off + HD * DD + DD));
                vvv[0] = __ldcs((const float4*)(Vc + off));
                vvv[1] = __ldcs((const float4*)(Vc + off + DD));
                vvv[2] = __ldcs((const float4*)(Vc + off + HD * DD));
                vvv[3] = __ldcs((const float4*)(Vc + off + HD * DD + DD));
                if (tb == pos)     { kk[0] = kr[0]; kk[1] = kr[1]; vvv[0] = vv4[0]; vvv[1] = vv4[1]; }
                if (tb + 1 == pos) { kk[2] = kr[0]; kk[3] = kr[1]; vvv[2] = vv4[0]; vvv[3] = vv4[1]; }

                float dot[4];
                dot[0] = qr[0].x*kk[0].x + qr[0].y*kk[0].y + qr[0].z*kk[0].z + qr[0].w*kk[0].w;
                dot[1] = qr[1].x*kk[1].x + qr[1].y*kk[1].y + qr[1].z*kk[1].z + qr[1].w*kk[1].w;
                dot[2] = qr[0].x*kk[2].x + qr[0].y*kk[2].y + qr[0].z*kk[2].z + qr[0].w*kk[2].w;
                dot[3] = qr[1].x*kk[3].x + qr[1].y*kk[3].y + qr[1].z*kk[3].z + qr[1].w*kk[3].w;
                #pragma unroll
                for (int o = 16; o > 0; o >>= 1) {
                    #pragma unroll
                    for (int j = 0; j < 4; j++)
                        dot[j] += __shfl_xor_sync(~0u, dot[j], o);
                }
                const float2 mk2 = __ldg((const float2*)(mk + tb));   // tb even
                const bool t1ok = (tb + 1 < s1);

                // head 0: scores for tokens tb, tb+1
                {
                    const float sa = dot[0] + mk2.x;
                    const float sb = t1ok ? dot[2] + mk2.y : NEGBIG;
                    const float mnew = fmaxf(m0, fmaxf(sa, sb));
                    const float corr = __expf(m0 - mnew);
                    const float pa = __expf(sa - mnew);
                    float pb = __expf(sb - mnew);
                    if (!t1ok) pb = 0.f;
                    l0 = l0 * corr + pa + pb;
                    acc0.x = acc0.x * corr + pa * vvv[0].x + pb * vvv[2].x;
                    acc0.y = acc0.y * corr + pa * vvv[0].y + pb * vvv[2].y;
                    acc0.z = acc0.z * corr + pa * vvv[0].z + pb * vvv[2].z;
                    acc0.w = acc0.w * corr + pa * vvv[0].w + pb * vvv[2].w;
                    m0 = mnew;
                }
                // head 1
                {
                    const float sa = dot[1] + mk2.x;
                    const float sb = t1ok ? dot[3] + mk2.y : NEGBIG;
                    const float mnew = fmaxf(m1, fmaxf(sa, sb));
                    const float corr = __expf(m1 - mnew);
                    const float pa = __expf(sa - mnew);
                    float pb = __expf(sb - mnew);
                    if (!t1ok) pb = 0.f;
                    l1 = l1 * corr + pa + pb;
                    acc1.x = acc1.x * corr + pa * vvv[1].x + pb * vvv[3].x;
                    acc1.y = acc1.y * corr + pa * vvv[1].y + pb * vvv[3].y;
                    acc1.z = acc1.z * corr + pa * vvv[1].z + pb * vvv[3].z;
                    acc1.w = acc1.w * corr + pa * vvv[1].w + pb * vvv[3].w;
                    m1 = mnew;
                }
            }
        }

        // --- combine the 4 warps' partials, per head ---
        __shared__ float sm_m[2][4], sm_l[2][4], sm_a[2][4 * DD];
        {
            float* d0 = sm_a[0] + warp * DD + 4 * lane;
            float* d1 = sm_a[1] + warp * DD + 4 * lane;
            d0[0]=acc0.x; d0[1]=acc0.y; d0[2]=acc0.z; d0[3]=acc0.w;
            d1[0]=acc1.x; d1[1]=acc1.y; d1[2]=acc1.z; d1[3]=acc1.w;
            if (lane == 0) {
                sm_m[0][warp] = m0; sm_l[0][warp] = l0;
                sm_m[1][warp] = m1; sm_l[1][warp] = l1;
            }
        }
        __syncthreads();

        #pragma unroll
        for (int e = 0; e < 2; e++) {
            const float M = fmaxf(fmaxf(sm_m[e][0], sm_m[e][1]),
                                  fmaxf(sm_m[e][2], sm_m[e][3]));
            float Lt = 0.f, a = 0.f;
            #pragma unroll
            for (int w = 0; w < 4; w++) {
                const float wl = sm_l[e][w];
                const float wf = (wl > 0.f) ? __expf(sm_m[e][w] - M) : 0.f;
                Lt += wf * wl;
                a  += wf * sm_a[e][w * DD + tid];
            }
            const int pidx = (bh0 + e) * NSPLIT + split;
            if (tid == 0) { g_pm[pidx] = M; g_pl[pidx] = Lt; }
            g_pacc[pidx * DD + tid] = a;
        }
    }
    // empty splits write NOTHING: combiner uses nvalid = ceil(L/CHUNK)

    // --- threadfence reduction: last split CTA combines & writes output ---
    __shared__ unsigned s_last;
    __threadfence();
    __syncthreads();
    if (tid == 0)
        s_last = (atomicAdd(&g_cnt[b * NHP + hp], 1u) == NSPLIT - 1u) ? 1u : 0u;
    __syncthreads();

    if (s_last) {
        const int nvalid = (L + CHUNK - 1) / CHUNK;   // valid splits
        #pragma unroll
        for (int e = 0; e < 2; e++) {
            const int base = (bh0 + e) * NSPLIT;

            float M = NEGBIG;
            for (int i = 0; i < nvalid; i++) M = fmaxf(M, g_pm[base + i]);

            float Lt = 0.f, a = 0.f;
            for (int i = 0; i < nvalid; i++) {
                const float w = __expf(g_pm[base + i] - M);
                Lt += w * g_pl[base + i];
                a  += w * g_pacc[(base + i) * DD + tid];
            }
            out[(bh0 + e) * DD + tid] = a / Lt;
        }
        if (tid == 0) g_cnt[b * NHP + hp] = 0u;   // self-reset for replay
    }
}

// ---------------------------------------------------------------------------
extern "C" void kernel_launch(void* const* d_in, const int* in_sizes, int n_in,
                              void* d_out, int out_size)
{
    const float* Q    = (const float*)d_in[0];
    const float* K    = (const float*)d_in[1];
    const float* V    = (const float*)d_in[2];
    const float* Kc   = (const float*)d_in[3];
    const float* Vc   = (const float*)d_in[4];
    const float* cosb = (const float*)d_in[5];
    const float* sinb = (const float*)d_in[6];
    const float* mask = (const float*)d_in[7];
    const int*   ilen = (const int*)d_in[8];
    // d_in[9] = save_slots — unused (fresh token is at input_length-1)
    const int*   btab = (const int*)d_in[10];
    (void)in_sizes; (void)n_in; (void)out_size;

    dim3 g1(NSPLIT, NHP, BD);
    attn_fused<<<g1, 128>>>(Q, K, V, Kc, Vc, cosb, sinb, mask, ilen, btab,
                            (float*)d_out);
}

// round 12
// speedup vs baseline: 1.2943x; 1.2943x over previous
#include <cuda_runtime.h>
#include <math.h>

// Problem constants (fixed by reference setup)
#define BD     16      // batch
#define HD     16      // heads
#define DD     128     // head dim
#define BLKD   16      // tokens per cache block
#define MAXBD  128     // blocks per sequence
#define MAXSD  2048    // max sequence length
#define NSPLIT 8       // token splits per (b,h)
#define CHUNK  256     // tokens per split
#define WTOK   64      // contiguous tokens per warp (4 blocks of 16)
#define SOFTMAX_SCALE 0.088388347648318447f  // 1/sqrt(128)
#define NEGBIG (-1e30f)

// Partial-result scratch (allocation-free: __device__ globals, zero-init .bss)
__device__ float g_pm[BD * HD * NSPLIT];
__device__ float g_pl[BD * HD * NSPLIT];
__device__ float g_pacc[BD * HD * NSPLIT * DD];      // 1 MB
__device__ unsigned int g_cnt[BD * HD];              // self-resetting counters

// ---------------------------------------------------------------------------
// Split-KV decode attention, single-wave scheduling.
//  grid (NSPLIT=8, HD, BD) = 2048 CTAs; non-empty ~= sum(ceil(L/256))*16
//  ~= 1150 =~ ONE wave at 8 CTAs/SM. 128 threads = 4 warps; warp w owns
//  CONTIGUOUS tokens [s0+64w, s0+64w+64) processed as 4 cache blocks of 16
//  tokens; the block-table entry is loaded once per block (R9: hoist depth
//  is perf-neutral). Inner engine is the proven 4-token/8-LDG.128 batch:
//  addresses are register arithmetic, __ldcs evict-first streaming loads,
//  group-max online softmax, out-of-range tokens masked with p=0.
//  Empty splits write NO scratch; combiner uses nvalid = ceil(L/CHUNK).
//  Fresh token (s == L-1) substitutes register-roped K / raw V.
//  Last split CTA per (b,h) (threadfence reduction) combines partials,
//  writes output, resets its counter (graph-replay deterministic).
// ---------------------------------------------------------------------------
__global__ __launch_bounds__(128, 8) void attn_fused(
    const float* __restrict__ Q,  const float* __restrict__ K,
    const float* __restrict__ V,  const float* __restrict__ Kc,
    const float* __restrict__ Vc, const float* __restrict__ cosb,
    const float* __restrict__ sinb, const float* __restrict__ mask,
    const int* __restrict__ ilen, const int* __restrict__ btab,
    float* __restrict__ out)
{
    const int split = blockIdx.x, h = blockIdx.y, b = blockIdx.z;
    const int tid = threadIdx.x, warp = tid >> 5, lane = tid & 31;
    const int bh   = b * HD + h;
    const int pidx = bh * NSPLIT + split;
    const int L  = ilen[b];
    const int s0 = split * CHUNK;

    if (s0 < L) {
        const int s1  = (s0 + CHUNK < L) ? s0 + CHUNK : L;
        const int pos = L - 1;   // fresh-token position

        // --- RoPE on Q and K (registers) ---
        const float4 q4  = *(const float4*)(Q    + bh * DD + 4 * lane);
        const float4 k4  = *(const float4*)(K    + bh * DD + 4 * lane);
        const float4 vv4 = *(const float4*)(V    + bh * DD + 4 * lane);
        const float4 c4  = *(const float4*)(cosb + b * DD + 4 * lane);
        const float4 s4  = *(const float4*)(sinb + b * DD + 4 * lane);

        const float sgn = (lane < 16) ? -1.f : 1.f;   // rot = [-x2, x1]
        float4 qp, kp;
        qp.x = __shfl_xor_sync(~0u, q4.x, 16);  qp.y = __shfl_xor_sync(~0u, q4.y, 16);
        qp.z = __shfl_xor_sync(~0u, q4.z, 16);  qp.w = __shfl_xor_sync(~0u, q4.w, 16);
        kp.x = __shfl_xor_sync(~0u, k4.x, 16);  kp.y = __shfl_xor_sync(~0u, k4.y, 16);
        kp.z = __shfl_xor_sync(~0u, k4.z, 16);  kp.w = __shfl_xor_sync(~0u, k4.w, 16);

        float4 qr, kr;   // qr pre-scaled by softmax scale
        qr.x = (q4.x * c4.x + sgn * qp.x * s4.x) * SOFTMAX_SCALE;
        qr.y = (q4.y * c4.y + sgn * qp.y * s4.y) * SOFTMAX_SCALE;
        qr.z = (q4.z * c4.z + sgn * qp.z * s4.z) * SOFTMAX_SCALE;
        qr.w = (q4.w * c4.w + sgn * qp.w * s4.w) * SOFTMAX_SCALE;
        kr.x =  k4.x * c4.x + sgn * kp.x * s4.x;
        kr.y =  k4.y * c4.y + sgn * kp.y * s4.y;
        kr.z =  k4.z * c4.z + sgn * kp.z * s4.z;
        kr.w =  k4.w * c4.w + sgn * kp.w * s4.w;

        const float* mk  = mask + b * MAXSD;
        const int*   bt  = btab + b * MAXBD;
        const int    ws0 = s0 + WTOK * warp;          // warp's first token

        float m = NEGBIG, l = 0.f;
        float4 acc = make_float4(0.f, 0.f, 0.f, 0.f);

        // 4 cache blocks of 16 tokens each
        for (int blk = 0; blk < WTOK / BLKD; blk++) {
            const int b0 = ws0 + BLKD * blk;          // block's first token
            if (b0 >= s1) break;                      // warp-uniform
            const int e    = __ldg(bt + (b0 >> 4));   // one entry per block
            const int offb = (e * BLKD * HD + h) * DD + 4 * lane;

            #pragma unroll
            for (int k2 = 0; k2 < 4; k2++) {
                const int tb = b0 + 4 * k2;           // 4 consecutive tokens
                if (tb >= s1) break;                  // warp-uniform
                const int off0 = offb + 4 * k2 * (HD * DD);

                float4 kk[4], vv[4];
                #pragma unroll
                for (int j = 0; j < 4; j++) {
                    const int  off = off0 + j * (HD * DD);
                    const bool sp  = (tb + j == pos);
                    kk[j] = sp ? kr  : __ldcs((const float4*)(Kc + off));
                    vv[j] = sp ? vv4 : __ldcs((const float4*)(Vc + off));
                }
                const float4 mk4 = __ldg((const float4*)(mk + tb)); // uniform

                float dot[4];
                #pragma unroll
                for (int j = 0; j < 4; j++)
                    dot[j] = qr.x * kk[j].x + qr.y * kk[j].y
                           + qr.z * kk[j].z + qr.w * kk[j].w;
                #pragma unroll
                for (int o = 16; o > 0; o >>= 1) {
                    #pragma unroll
                    for (int j = 0; j < 4; j++)
                        dot[j] += __shfl_xor_sync(~0u, dot[j], o);
                }
                float sc[4];
                sc[0] = (tb     < s1) ? dot[0] + mk4.x : NEGBIG;
                sc[1] = (tb + 1 < s1) ? dot[1] + mk4.y : NEGBIG;
                sc[2] = (tb + 2 < s1) ? dot[2] + mk4.z : NEGBIG;
                sc[3] = (tb + 3 < s1) ? dot[3] + mk4.w : NEGBIG;

                const float gm   = fmaxf(fmaxf(sc[0], sc[1]), fmaxf(sc[2], sc[3]));
                const float mnew = fmaxf(m, gm);
                const float corr = __expf(m - mnew);
                float p[4];
                #pragma unroll
                for (int j = 0; j < 4; j++) {
                    p[j] = __expf(sc[j] - mnew);
                    if (tb + j >= s1) p[j] = 0.f;
                }
                l = l * corr + ((p[0] + p[1]) + (p[2] + p[3]));
                acc.x = acc.x * corr + (p[0]*vv[0].x + p[1]*vv[1].x + p[2]*vv[2].x + p[3]*vv[3].x);
                acc.y = acc.y * corr + (p[0]*vv[0].y + p[1]*vv[1].y + p[2]*vv[2].y + p[3]*vv[3].y);
                acc.z = acc.z * corr + (p[0]*vv[0].z + p[1]*vv[1].z + p[2]*vv[2].z + p[3]*vv[3].z);
                acc.w = acc.w * corr + (p[0]*vv[0].w + p[1]*vv[1].w + p[2]*vv[2].w + p[3]*vv[3].w);
                m = mnew;
            }
        }

        // --- combine the 4 warps' partials ---
        __shared__ float sm_m[4], sm_l[4], sm_a[4 * DD];
        float* dst = sm_a + warp * DD + 4 * lane;
        dst[0] = acc.x; dst[1] = acc.y; dst[2] = acc.z; dst[3] = acc.w;
        if (lane == 0) { sm_m[warp] = m; sm_l[warp] = l; }
        __syncthreads();

        const float M = fmaxf(fmaxf(sm_m[0], sm_m[1]), fmaxf(sm_m[2], sm_m[3]));
        float Lt = 0.f, a = 0.f;
        #pragma unroll
        for (int w = 0; w < 4; w++) {
            const float wl = sm_l[w];
            const float wf = (wl > 0.f) ? __expf(sm_m[w] - M) : 0.f;
            Lt += wf * wl;
            a  += wf * sm_a[w * DD + tid];
        }
        if (tid == 0) { g_pm[pidx] = M; g_pl[pidx] = Lt; }
        g_pacc[pidx * DD + tid] = a;
    }
    // empty splits write NOTHING: combiner uses nvalid = ceil(L/CHUNK)

    // --- threadfence reduction: last split CTA combines & writes output ---
    __shared__ unsigned s_last;
    __threadfence();
    __syncthreads();
    if (tid == 0)
        s_last = (atomicAdd(&g_cnt[bh], 1u) == NSPLIT - 1u) ? 1u : 0u;
    __syncthreads();

    if (s_last) {
        const int nvalid = (L + CHUNK - 1) / CHUNK;   // valid splits for bh
        const int base   = bh * NSPLIT;

        float M = NEGBIG;
        for (int i = 0; i < nvalid; i++) M = fmaxf(M, g_pm[base + i]);

        float Lt = 0.f, a = 0.f;
        for (int i = 0; i < nvalid; i++) {
            const float w = __expf(g_pm[base + i] - M);
            Lt += w * g_pl[base + i];
            a  += w * g_pacc[(base + i) * DD + tid];
        }
        out[bh * DD + tid] = a / Lt;
        if (tid == 0) g_cnt[bh] = 0u;   // self-reset for next graph replay
    }
}

// ---------------------------------------------------------------------------
extern "C" void kernel_launch(void* const* d_in, const int* in_sizes, int n_in,
                              void* d_out, int out_size)
{
    const float* Q    = (const float*)d_in[0];
    const float* K    = (const float*)d_in[1];
    const float* V    = (const float*)d_in[2];
    const float* Kc   = (const float*)d_in[3];
    const float* Vc   = (const float*)d_in[4];
    const float* cosb = (const float*)d_in[5];
    const float* sinb = (const float*)d_in[6];
    const float* mask = (const float*)d_in[7];
    const int*   ilen = (const int*)d_in[8];
    // d_in[9] = save_slots — unused (fresh token is at input_length-1)
    const int*   btab = (const int*)d_in[10];
    (void)in_sizes; (void)n_in; (void)out_size;

    dim3 g1(NSPLIT, HD, BD);
    attn_fused<<<g1, 128>>>(Q, K, V, Kc, Vc, cosb, sinb, mask, ilen, btab,
                            (float*)d_out);
}